// round 3
// baseline (speedup 1.0000x reference)
#include <cuda_runtime.h>

// Stickbreaking attention, fp32, B=2 H=16 S=1024 D=64.
//
// w[i,k] = exp( x_ik + lb_ik + S_ik ),  lb = logsigmoid(-x) <= 0,
//          S_ik = suffix sum of lb over keys k..i  (<= 0, stable).
// Stream key blocks DESCENDING, carrying per-row accumulator A_i.
//
// BQ=64 q-rows/CTA, BK=64 keys/block, 128 threads, 8x4 register tile.

#define SEQ     1024
#define DHEAD   64
#define BQ      64
#define BK      64
#define THREADS 128
#define NQB     (SEQ / BQ)   // 16 q-tiles

// XOR swizzle on float4 chunks: row r, chunk c4 (0..15)
__device__ __forceinline__ int swz(int r, int c4) {
    return r * 16 + (c4 ^ ((r >> 2) & 15));
}

__global__ __launch_bounds__(THREADS, 3)
void stickbreaking_kernel(const float* __restrict__ q,
                          const float* __restrict__ k,
                          const float* __restrict__ v,
                          float* __restrict__ out) {
    extern __shared__ float4 smem[];
    float4* Qs = smem;            // 64x16 = 1024 float4 (16 KB)
    float4* Ks = smem + 1024;     // 16 KB
    float4* Vs = smem + 2048;     // 16 KB
    float4* Ws = smem + 3072;     // 16 KB

    const int tid = threadIdx.x;
    const int rg  = tid >> 4;     // 0..7 : rows 8*rg .. 8*rg+7
    const int kg  = tid & 15;     // 0..15: keys 4*kg .. 4*kg+3
    const int bh  = blockIdx.y;
    const int qb  = (NQB - 1) - blockIdx.x;   // heaviest tiles first
    const int qbase = qb * BQ;

    const float* qb_base = q   + (size_t)bh * SEQ * DHEAD;
    const float* kb_base = k   + (size_t)bh * SEQ * DHEAD;
    const float* vb_base = v   + (size_t)bh * SEQ * DHEAD;
    float*       ob_base = out + (size_t)bh * SEQ * DHEAD;

    // ---- load Q tile [BQ x 64], swizzled ----
    {
        const float4* g = (const float4*)(qb_base + (size_t)qbase * DHEAD);
        #pragma unroll
        for (int i = 0; i < 8; i++) {
            int f = i * THREADS + tid;   // 0..1023
            int r = f >> 4, c4 = f & 15;
            Qs[swz(r, c4)] = g[f];
        }
    }

    float acc[8][4];
    #pragma unroll
    for (int i = 0; i < 8; i++)
        #pragma unroll
        for (int j = 0; j < 4; j++) acc[i][j] = 0.f;
    float A[8];
    #pragma unroll
    for (int i = 0; i < 8; i++) A[i] = 0.f;

    const int nkb = qb + 1;  // key blocks covering keys 0 .. qbase+63

    #pragma unroll 1
    for (int kb = nkb - 1; kb >= 0; --kb) {
        const int kbase = kb * BK;
        const bool diag = (kb == qb);

        __syncthreads();  // prev PV done before overwriting K/V (also orders Q store)
        {
            const float4* gk = (const float4*)(kb_base + (size_t)kbase * DHEAD);
            const float4* gv = (const float4*)(vb_base + (size_t)kbase * DHEAD);
            #pragma unroll
            for (int i = 0; i < 8; i++) {
                int f = i * THREADS + tid;
                int r = f >> 4, c4 = f & 15;
                Ks[swz(r, c4)] = gk[f];
                Vs[swz(r, c4)] = gv[f];
            }
        }
        __syncthreads();

        // ---- QK^T : 8x4 score tile per thread ----
        float s[8][4];
        #pragma unroll
        for (int i = 0; i < 8; i++)
            #pragma unroll
            for (int j = 0; j < 4; j++) s[i][j] = 0.f;

        #pragma unroll
        for (int d4 = 0; d4 < 16; ++d4) {
            float4 qv[8], kv[4];
            #pragma unroll
            for (int i = 0; i < 8; i++)
                qv[i] = Qs[(8 * rg + i) * 16 + (d4 ^ ((2 * rg + (i >> 2)) & 15))];
            #pragma unroll
            for (int j = 0; j < 4; j++)
                kv[j] = Ks[(4 * kg + j) * 16 + (d4 ^ kg)];
            #pragma unroll
            for (int i = 0; i < 8; i++)
                #pragma unroll
                for (int j = 0; j < 4; j++) {
                    s[i][j] = fmaf(qv[i].x, kv[j].x, s[i][j]);
                    s[i][j] = fmaf(qv[i].y, kv[j].y, s[i][j]);
                    s[i][j] = fmaf(qv[i].z, kv[j].z, s[i][j]);
                    s[i][j] = fmaf(qv[i].w, kv[j].w, s[i][j]);
                }
        }

        // ---- elementwise + per-row suffix scan (16 lanes per row group) ----
        const unsigned li = (unsigned)kg;
        #pragma unroll
        for (int i = 0; i < 8; i++) {
            const int row_g = qbase + 8 * rg + i;
            float lb[4], c[4];
            #pragma unroll
            for (int j = 0; j < 4; j++) {
                float xx = s[i][j] * 0.125f;  // 1/sqrt(64)
                float l  = -(fmaxf(xx, 0.f) + __logf(1.f + __expf(-fabsf(xx))));
                if (diag) {
                    bool valid = (kbase + 4 * kg + j) <= row_g;
                    lb[j] = valid ? l : 0.f;
                    c[j]  = valid ? (xx + l) : -1e30f;
                } else {
                    lb[j] = l;
                    c[j]  = xx + l;
                }
            }
            float tloc = lb[0] + lb[1] + lb[2] + lb[3];
            float incl = tloc;  // inclusive suffix sum over 16 lanes
            #pragma unroll
            for (int dlt = 1; dlt < 16; dlt <<= 1) {
                float o = __shfl_down_sync(0xffffffffu, incl, dlt, 16);
                if (li + dlt < 16) incl += o;
            }
            float total = __shfl_sync(0xffffffffu, incl, 0, 16);
            float run = A[i] + (incl - tloc);  // lb over keys with higher kg
            float wv0, wv1, wv2, wv3;
            run += lb[3]; wv3 = __expf(c[3] + run);
            run += lb[2]; wv2 = __expf(c[2] + run);
            run += lb[1]; wv1 = __expf(c[1] + run);
            run += lb[0]; wv0 = __expf(c[0] + run);
            A[i] += total;
            Ws[(8 * rg + i) * 16 + (kg ^ ((2 * rg + (i >> 2)) & 15))] =
                make_float4(wv0, wv1, wv2, wv3);
        }
        __syncwarp();  // producers/consumers of a row group share a 16-lane group

        // ---- PV : acc[8 rows][4 dims] += W[8 rows][:] * V[:][4 dims] ----
        #pragma unroll
        for (int j4 = 0; j4 < 16; ++j4) {
            float4 w4[8];
            #pragma unroll
            for (int i = 0; i < 8; i++)
                w4[i] = Ws[(8 * rg + i) * 16 + (j4 ^ ((2 * rg + (i >> 2)) & 15))];
            #pragma unroll
            for (int m = 0; m < 4; m++) {
                float4 vm = Vs[(4 * j4 + m) * 16 + (kg ^ j4)];
                #pragma unroll
                for (int i = 0; i < 8; i++) {
                    float wm = (m == 0) ? w4[i].x : (m == 1) ? w4[i].y
                             : (m == 2) ? w4[i].z : w4[i].w;
                    acc[i][0] = fmaf(wm, vm.x, acc[i][0]);
                    acc[i][1] = fmaf(wm, vm.y, acc[i][1]);
                    acc[i][2] = fmaf(wm, vm.z, acc[i][2]);
                    acc[i][3] = fmaf(wm, vm.w, acc[i][3]);
                }
            }
        }
        __syncwarp();  // Ws reads done before next iteration's writes
    }

    // ---- write output tile (coalesced float4) ----
    #pragma unroll
    for (int i = 0; i < 8; i++) {
        float4 o = make_float4(acc[i][0], acc[i][1], acc[i][2], acc[i][3]);
        ((float4*)(ob_base + (size_t)(qbase + 8 * rg + i) * DHEAD))[kg] = o;
    }
}

extern "C" void kernel_launch(void* const* d_in, const int* in_sizes, int n_in,
                              void* d_out, int out_size) {
    const float* q = (const float*)d_in[0];
    const float* k = (const float*)d_in[1];
    const float* v = (const float*)d_in[2];
    float* out = (float*)d_out;
    (void)in_sizes; (void)n_in; (void)out_size;

    const int smem_bytes = 4096 * 16;  // 64 KB dynamic
    cudaFuncSetAttribute(stickbreaking_kernel,
                         cudaFuncAttributeMaxDynamicSharedMemorySize, smem_bytes);

    dim3 grid(NQB, 32);   // 16 q-tiles (heaviest first) x (B*H = 32)
    dim3 block(THREADS);
    stickbreaking_kernel<<<grid, block, smem_bytes>>>(q, k, v, out);
}

// round 5
// speedup vs baseline: 3.1723x; 3.1723x over previous
#include <cuda_runtime.h>
#include <cuda_bf16.h>
#include <cstdint>

// Stickbreaking attention via mma.sync (HMMA) bf16-split. B=2 H=16 S=1024 D=64.
// w[i,k] = exp( x_ik + 2*lb_ik + sum_{k<j<=i} lb_ij ), lb = logsigmoid(-x).
// Key blocks streamed descending; per-row carry A accumulates lb of higher keys.

#define SEQ 1024
#define DH 64
#define BQ 64
#define BK 64
#define THREADS 128
#define NQB (SEQ / BQ)
#define FULL 0xffffffffu

#define KH_OFF 0
#define KL_OFF 8192
#define VH_OFF 16384
#define VL_OFF 24576

__device__ __forceinline__ uint32_t smem_u32(const void* p) {
    uint32_t a;
    asm("{ .reg .u64 t; cvta.to.shared.u64 t, %1; cvt.u32.u64 %0, t; }" : "=r"(a) : "l"(p));
    return a;
}

#define MMA(d, a, b0, b1) \
    asm volatile("mma.sync.aligned.m16n8k16.row.col.f32.bf16.bf16.f32 " \
        "{%0,%1,%2,%3}, {%4,%5,%6,%7}, {%8,%9}, {%0,%1,%2,%3};" \
        : "+f"((d)[0]), "+f"((d)[1]), "+f"((d)[2]), "+f"((d)[3]) \
        : "r"((a)[0]), "r"((a)[1]), "r"((a)[2]), "r"((a)[3]), "r"(b0), "r"(b1))

#define LDSM4(r, addr) \
    asm volatile("ldmatrix.sync.aligned.m8n8.x4.shared.b16 {%0,%1,%2,%3}, [%4];" \
        : "=r"((r)[0]), "=r"((r)[1]), "=r"((r)[2]), "=r"((r)[3]) : "r"(addr))

#define LDSM4T(r, addr) \
    asm volatile("ldmatrix.sync.aligned.m8n8.x4.trans.shared.b16 {%0,%1,%2,%3}, [%4];" \
        : "=r"((r)[0]), "=r"((r)[1]), "=r"((r)[2]), "=r"((r)[3]) : "r"(addr))

__device__ __forceinline__ uint32_t pack2(__nv_bfloat16 lo, __nv_bfloat16 hi) {
    __nv_bfloat162 t(lo, hi);
    return *reinterpret_cast<uint32_t*>(&t);
}
__device__ __forceinline__ void split2(float x, __nv_bfloat16& h, __nv_bfloat16& l) {
    h = __float2bfloat16_rn(x);
    l = __float2bfloat16_rn(x - __bfloat162float(h));
}

__global__ __launch_bounds__(THREADS)
void sb_mma(const float* __restrict__ q, const float* __restrict__ k,
            const float* __restrict__ v, float* __restrict__ out) {
    __shared__ __align__(16) char smem[32768];
    const uint32_t sb = smem_u32(smem);
    const int tid = threadIdx.x;
    const int lane = tid & 31, warp = tid >> 5;
    const int q4 = lane & 3, rowA = lane >> 2;   // quad col idx, row-in-8
    const int sel = lane >> 3, rr = lane & 7;    // ldmatrix matrix select / row

    const int idx = blockIdx.x;
    const int qb = (NQB - 1) - (idx >> 5);       // heaviest q-tiles first
    const int bh = idx & 31;
    const int qbase = qb * BQ;

    const float* qg = q + (size_t)bh * SEQ * DH;
    const float* kg = k + (size_t)bh * SEQ * DH;
    const float* vg = v + (size_t)bh * SEQ * DH;
    float* og = out + (size_t)bh * SEQ * DH;

    // ---- stage Q tile (bf16 hi/lo) into KH/KL buffers, XOR-swizzled ----
    {
        const float4* gq = (const float4*)(qg + (size_t)qbase * DH);
        #pragma unroll
        for (int i = 0; i < 8; i++) {
            int f = i * THREADS + tid;
            int row = f >> 4, c4 = f & 15;
            float4 x = gq[f];
            __nv_bfloat16 h0, h1, h2, h3, l0, l1, l2, l3;
            split2(x.x, h0, l0); split2(x.y, h1, l1);
            split2(x.z, h2, l2); split2(x.w, h3, l3);
            uint32_t off = (uint32_t)(row * 128 + (((c4 >> 1) ^ (row & 7)) << 4) + (c4 & 1) * 8);
            *(uint2*)(smem + KH_OFF + off) = make_uint2(pack2(h0, h1), pack2(h2, h3));
            *(uint2*)(smem + KL_OFF + off) = make_uint2(pack2(l0, l1), pack2(l2, l3));
        }
    }
    __syncthreads();

    // ---- load persistent Q A-fragments (hi & lo), 4 k-chunks ----
    uint32_t qh[4][4], ql[4][4];
    {
        int row = warp * 16 + (sel & 1) * 8 + rr;
        #pragma unroll
        for (int kc = 0; kc < 4; kc++) {
            int chunk = 2 * kc + (sel >> 1);
            uint32_t a = sb + (uint32_t)(row * 128 + ((chunk ^ rr) << 4));
            LDSM4(qh[kc], a + KH_OFF);
            LDSM4(ql[kc], a + KL_OFF);
        }
    }

    float o[8][4];
    #pragma unroll
    for (int nt = 0; nt < 8; nt++) { o[nt][0] = o[nt][1] = o[nt][2] = o[nt][3] = 0.f; }
    float A0 = 0.f, A1 = 0.f;
    const int wr0 = qbase + warp * 16 + rowA;    // global row (r0); r1 = wr0+8

    #pragma unroll 1
    for (int kb = qb; kb >= 0; --kb) {
        const int kbase = kb * BK;

        // -- prefetch K/V block to regs (16 LDG.128, high MLP) --
        float4 kr[8], vr[8];
        {
            const float4* gk = (const float4*)(kg + (size_t)kbase * DH);
            const float4* gv = (const float4*)(vg + (size_t)kbase * DH);
            #pragma unroll
            for (int i = 0; i < 8; i++) {
                int f = i * THREADS + tid;
                kr[i] = gk[f]; vr[i] = gv[f];
            }
        }
        __syncthreads();   // all smem reads of previous block done
        #pragma unroll
        for (int i = 0; i < 8; i++) {
            int f = i * THREADS + tid;
            int row = f >> 4, c4 = f & 15;
            uint32_t off = (uint32_t)(row * 128 + (((c4 >> 1) ^ (row & 7)) << 4) + (c4 & 1) * 8);
            __nv_bfloat16 h0, h1, h2, h3, l0, l1, l2, l3;
            split2(kr[i].x, h0, l0); split2(kr[i].y, h1, l1);
            split2(kr[i].z, h2, l2); split2(kr[i].w, h3, l3);
            *(uint2*)(smem + KH_OFF + off) = make_uint2(pack2(h0, h1), pack2(h2, h3));
            *(uint2*)(smem + KL_OFF + off) = make_uint2(pack2(l0, l1), pack2(l2, l3));
            split2(vr[i].x, h0, l0); split2(vr[i].y, h1, l1);
            split2(vr[i].z, h2, l2); split2(vr[i].w, h3, l3);
            *(uint2*)(smem + VH_OFF + off) = make_uint2(pack2(h0, h1), pack2(h2, h3));
            *(uint2*)(smem + VL_OFF + off) = make_uint2(pack2(l0, l1), pack2(l2, l3));
        }
        __syncthreads();

        // ---- QK^T: D[16 rows x 64 keys], 3 split passes ----
        float d[8][4];
        #pragma unroll
        for (int nt = 0; nt < 8; nt++) { d[nt][0] = d[nt][1] = d[nt][2] = d[nt][3] = 0.f; }

        #pragma unroll
        for (int kc = 0; kc < 4; kc++) {
            uint32_t kf[16];
            const int keyl = (sel >> 1) * 8 + rr;
            const int chunk = 2 * kc + (sel & 1);
            #pragma unroll
            for (int p = 0; p < 4; p++) {
                uint32_t a = sb + KH_OFF + (uint32_t)((p * 16 + keyl) * 128 + ((chunk ^ rr) << 4));
                LDSM4(&kf[p * 4], a);
            }
            #pragma unroll
            for (int nt = 0; nt < 8; nt++) MMA(d[nt], qh[kc], kf[nt * 2], kf[nt * 2 + 1]);
            #pragma unroll
            for (int nt = 0; nt < 8; nt++) MMA(d[nt], ql[kc], kf[nt * 2], kf[nt * 2 + 1]);
            #pragma unroll
            for (int p = 0; p < 4; p++) {
                uint32_t a = sb + KL_OFF + (uint32_t)((p * 16 + keyl) * 128 + ((chunk ^ rr) << 4));
                LDSM4(&kf[p * 4], a);
            }
            #pragma unroll
            for (int nt = 0; nt < 8; nt++) MMA(d[nt], qh[kc], kf[nt * 2], kf[nt * 2 + 1]);
        }

        // ---- stickbreaking scan (quad shuffles), W -> bf16 A-fragments ----
        uint32_t wha[4][4], wla[4][4];
        const bool diag = (kb == qb);
        #pragma unroll
        for (int nt = 7; nt >= 0; --nt) {
            const int keyA = kbase + nt * 8 + 2 * q4;
            #pragma unroll
            for (int rs = 0; rs < 2; rs++) {
                float xa = d[nt][rs * 2 + 0] * 0.125f;   // 1/sqrt(64)
                float xb = d[nt][rs * 2 + 1] * 0.125f;
                float la = -(fmaxf(xa, 0.f) + __logf(1.f + __expf(-fabsf(xa))));
                float lb = -(fmaxf(xb, 0.f) + __logf(1.f + __expf(-fabsf(xb))));
                float ca = xa + la, cb = xb + lb;
                if (diag) {
                    const int rowg = wr0 + rs * 8;
                    if (keyA > rowg)     { la = 0.f; ca = -1e30f; }
                    if (keyA + 1 > rowg) { lb = 0.f; cb = -1e30f; }
                }
                float s2 = la + lb;
                float u = s2;                                     // quad suffix scan
                float t1 = __shfl_down_sync(FULL, u, 1, 4);
                u = (q4 < 3) ? u + t1 : u;
                float t2 = __shfl_down_sync(FULL, u, 2, 4);
                u = (q4 < 2) ? u + t2 : u;
                float tot = __shfl_sync(FULL, u, 0, 4);
                float& A = rs ? A1 : A0;
                float hi = A + (u - s2);                          // lb of higher lanes
                float wb = __expf(cb + lb + hi);
                float wa = __expf(ca + la + lb + hi);
                A += tot;
                __nv_bfloat16 ah, al, bh2, bl2;
                split2(wa, ah, al); split2(wb, bh2, bl2);
                wha[nt >> 1][(nt & 1) * 2 + rs] = pack2(ah, bh2);
                wla[nt >> 1][(nt & 1) * 2 + rs] = pack2(al, bl2);
            }
        }

        // ---- PV: O += W * V (V via ldmatrix.trans), 3 split passes ----
        #pragma unroll
        for (int kc = 0; kc < 4; kc++) {
            uint32_t vf[16];
            const int keyv = kc * 16 + (sel & 1) * 8 + rr;
            #pragma unroll
            for (int p = 0; p < 4; p++) {
                int chunk = 2 * p + (sel >> 1);
                uint32_t a = sb + VH_OFF + (uint32_t)(keyv * 128 + ((chunk ^ rr) << 4));
                LDSM4T(&vf[p * 4], a);
            }
            #pragma unroll
            for (int nt = 0; nt < 8; nt++) MMA(o[nt], wha[kc], vf[nt * 2], vf[nt * 2 + 1]);
            #pragma unroll
            for (int nt = 0; nt < 8; nt++) MMA(o[nt], wla[kc], vf[nt * 2], vf[nt * 2 + 1]);
            #pragma unroll
            for (int p = 0; p < 4; p++) {
                int chunk = 2 * p + (sel >> 1);
                uint32_t a = sb + VL_OFF + (uint32_t)(keyv * 128 + ((chunk ^ rr) << 4));
                LDSM4T(&vf[p * 4], a);
            }
            #pragma unroll
            for (int nt = 0; nt < 8; nt++) MMA(o[nt], wha[kc], vf[nt * 2], vf[nt * 2 + 1]);
        }
    }

    // ---- write output: per-thread 2 rows x 16 cols as float2 ----
    {
        float* r0p = og + (size_t)wr0 * DH;
        float* r1p = og + (size_t)(wr0 + 8) * DH;
        #pragma unroll
        for (int nt = 0; nt < 8; nt++) {
            *(float2*)(r0p + nt * 8 + 2 * q4) = make_float2(o[nt][0], o[nt][1]);
            *(float2*)(r1p + nt * 8 + 2 * q4) = make_float2(o[nt][2], o[nt][3]);
        }
    }
}

extern "C" void kernel_launch(void* const* d_in, const int* in_sizes, int n_in,
                              void* d_out, int out_size) {
    const float* q = (const float*)d_in[0];
    const float* k = (const float*)d_in[1];
    const float* v = (const float*)d_in[2];
    float* out = (float*)d_out;
    (void)in_sizes; (void)n_in; (void)out_size;

    sb_mma<<<NQB * 32, THREADS>>>(q, k, v, out);  // 512 CTAs, heaviest first
}